// round 1
// baseline (speedup 1.0000x reference)
#include <cuda_runtime.h>
#include <math.h>

#define BB 8
#define CC 64
#define NN 4096
#define KK 32
#define NPTS (BB*NN)          // 32768
#define EPSB 1e-5f
#define NEG_INF (-3.4e38f)

// ---------------- device scratch (static, allocation-free) ----------------
__device__ float g_Pq[NPTS*CC];
__device__ float g_Pk[NPTS*CC];
__device__ float g_Pv[NPTS*CC];
__device__ float g_sq[NPTS];
__device__ float g_score[(size_t)NPTS*NN];   // 512 MB: ranking scores 2*G - sq[m]
__device__ int   g_idx[NPTS*KK];
__device__ float g_y1[(size_t)NPTS*CC];
__device__ float g_y2[(size_t)NPTS*CC];
__device__ float g_stats[256];               // [sum1|sumsq1|sum2|sumsq2] x 64ch

// ---------------- zero stats (graph-replay safe) ----------------
__global__ void k_zero() { g_stats[threadIdx.x] = 0.f; }

// ---------------- K1: feat projections Pq/Pk/Pv + sq ----------------
// grid 512 (b * 64 point-tiles), 256 threads, dyn smem 66560B
__global__ void k_proj(const float* __restrict__ x, const float* __restrict__ wq,
                       const float* __restrict__ wk, const float* __restrict__ wv) {
    extern __shared__ float sm[];
    float* sW = sm;              // 3 * 64*65, layout [w][c*65+o] (transposed, padded)
    float* sf = sm + 3*4160;     // 64*65, layout [p*65+c]
    int t = threadIdx.x;
    int b  = blockIdx.x >> 6;
    int n0 = (blockIdx.x & 63) * 64;
    const float* ws[3] = {wq, wk, wv};
#pragma unroll
    for (int w = 0; w < 3; w++)
#pragma unroll
        for (int s = 0; s < 16; s++) {
            int i = t + 256*s; int o = i >> 6, c = i & 63;
            sW[w*4160 + c*65 + o] = ws[w][i];
        }
    const float* xb = x + (size_t)b*CC*NN;
#pragma unroll
    for (int s = 0; s < 16; s++) {
        int i = t + 256*s; int c = i >> 6, p = i & 63;
        sf[p*65 + c] = xb[c*NN + n0 + p];
    }
    __syncthreads();
    if (t < 64) {
        float s = 0.f;
#pragma unroll
        for (int c = 0; c < 64; c++) { float v = sf[t*65+c]; s += v*v; }
        g_sq[b*NN + n0 + t] = s;
    }
    float* outs[3] = {g_Pq, g_Pk, g_Pv};
#pragma unroll
    for (int w = 0; w < 3; w++)
#pragma unroll
        for (int s = 0; s < 16; s++) {
            int i = t + 256*s; int p = i >> 6, o = i & 63;
            float acc = 0.f;
#pragma unroll
            for (int c = 0; c < 64; c++)
                acc += sf[p*65+c] * sW[w*4160 + c*65 + o];
            outs[w][(size_t)(b*NN + n0 + p)*CC + o] = acc;
        }
}

// ---------------- K2: symmetric distance-score GEMM ----------------
// s[n][m] = 2*dot(feat_n, feat_m) - sq[m]  (sq[n] omitted: rank-invariant)
// grid (32,32,8); only bx>=by computes; writes tile + mirrored tile.
__global__ void __launch_bounds__(256, 2)
k_dist(const float* __restrict__ x) {
    int bx = blockIdx.x, by = blockIdx.y, b = blockIdx.z;
    if (by > bx) return;
    extern __shared__ float sm[];
    float* As = sm;              // [k][i] 64 x 132
    float* Bs = sm + 64*132;
    int n0 = by*128, m0 = bx*128;
    const float* xb = x + (size_t)b*CC*NN;   // x is [c][n] = featT already
    int t = threadIdx.x;
#pragma unroll
    for (int s = 0; s < 32; s++) {
        int j = t + 256*s; int k = j >> 7, i = j & 127;
        As[k*132+i] = xb[k*NN + n0 + i];
        Bs[k*132+i] = xb[k*NN + m0 + i];
    }
    __syncthreads();
    int tx = t & 15, ty = t >> 4;
    float acc[8][8];
#pragma unroll
    for (int i=0;i<8;i++)
#pragma unroll
        for (int j=0;j<8;j++) acc[i][j]=0.f;
#pragma unroll 8
    for (int k = 0; k < 64; k++) {
        float av[8], bv[8];
        float4 a0 = *(const float4*)(As + k*132 + ty*8);
        float4 a1 = *(const float4*)(As + k*132 + ty*8 + 4);
        float4 b0 = *(const float4*)(Bs + k*132 + tx*8);
        float4 b1 = *(const float4*)(Bs + k*132 + tx*8 + 4);
        av[0]=a0.x; av[1]=a0.y; av[2]=a0.z; av[3]=a0.w;
        av[4]=a1.x; av[5]=a1.y; av[6]=a1.z; av[7]=a1.w;
        bv[0]=b0.x; bv[1]=b0.y; bv[2]=b0.z; bv[3]=b0.w;
        bv[4]=b1.x; bv[5]=b1.y; bv[6]=b1.z; bv[7]=b1.w;
#pragma unroll
        for (int i=0;i<8;i++)
#pragma unroll
            for (int j=0;j<8;j++) acc[i][j] += av[i]*bv[j];
    }
    const float* sqb = g_sq + b*NN;
    float sqm[8], sqn[8];
#pragma unroll
    for (int j=0;j<8;j++) sqm[j] = sqb[m0 + tx*8 + j];
#pragma unroll
    for (int i=0;i<8;i++) sqn[i] = sqb[n0 + ty*8 + i];
    float* base = g_score + (size_t)b*NN*NN;
#pragma unroll
    for (int i=0;i<8;i++) {
        int row = n0 + ty*8 + i;
        float* d = base + (size_t)row*NN + m0 + tx*8;
        float4 v0, v1;
        v0.x = 2.f*acc[i][0]-sqm[0]; v0.y = 2.f*acc[i][1]-sqm[1];
        v0.z = 2.f*acc[i][2]-sqm[2]; v0.w = 2.f*acc[i][3]-sqm[3];
        v1.x = 2.f*acc[i][4]-sqm[4]; v1.y = 2.f*acc[i][5]-sqm[5];
        v1.z = 2.f*acc[i][6]-sqm[6]; v1.w = 2.f*acc[i][7]-sqm[7];
        *(float4*)(d)   = v0;
        *(float4*)(d+4) = v1;
    }
    if (bx != by) {
#pragma unroll
        for (int j=0;j<8;j++) {
            int rowT = m0 + tx*8 + j;
            float* d = base + (size_t)rowT*NN + n0 + ty*8;
            float4 v0, v1;
            v0.x = 2.f*acc[0][j]-sqn[0]; v0.y = 2.f*acc[1][j]-sqn[1];
            v0.z = 2.f*acc[2][j]-sqn[2]; v0.w = 2.f*acc[3][j]-sqn[3];
            v1.x = 2.f*acc[4][j]-sqn[4]; v1.y = 2.f*acc[5][j]-sqn[5];
            v1.z = 2.f*acc[6][j]-sqn[6]; v1.w = 2.f*acc[7][j]-sqn[7];
            *(float4*)(d)   = v0;
            *(float4*)(d+4) = v1;
        }
    }
}

// ---------------- K3: top-32 selection per row ----------------
// grid 32768 blocks (one row), 256 threads; 32 rounds of cached block-argmax.
__global__ void k_topk() {
    __shared__ float sv[16*256];
    __shared__ float swv[8];
    __shared__ int   swm[8];
    __shared__ int   swin;
    int t = threadIdx.x;
    size_t row = blockIdx.x;
    const float* src = g_score + row*(size_t)NN;
#pragma unroll
    for (int i=0;i<16;i++) sv[i*256+t] = src[i*256+t];
    float lv = NEG_INF; int lm = 0;
#pragma unroll
    for (int i=0;i<16;i++){ float v = sv[i*256+t]; if (v > lv){ lv=v; lm=i*256+t; } }
    __syncthreads();
    for (int r=0;r<32;r++){
        float wv = lv; int wm = lm;
#pragma unroll
        for (int off=16; off>0; off>>=1){
            float ov = __shfl_down_sync(0xffffffffu, wv, off);
            int   om = __shfl_down_sync(0xffffffffu, wm, off);
            if (ov > wv || (ov == wv && om < wm)) { wv=ov; wm=om; }
        }
        if ((t & 31)==0){ swv[t>>5]=wv; swm[t>>5]=wm; }
        __syncthreads();
        if (t==0){
            float bv = swv[0]; int bm = swm[0];
#pragma unroll
            for (int w=1;w<8;w++){
                if (swv[w] > bv || (swv[w]==bv && swm[w]<bm)){ bv=swv[w]; bm=swm[w]; }
            }
            swin = bm;
            g_idx[row*KK + r] = bm;
        }
        __syncthreads();
        int winm = swin;
        if ((winm & 255) == t){
            sv[(winm >> 8)*256 + t] = NEG_INF;
            lv = NEG_INF; lm = 0;
#pragma unroll
            for (int i=0;i<16;i++){ float v = sv[i*256+t]; if (v>lv){ lv=v; lm=i*256+t; } }
        }
        __syncthreads();
    }
}

// ---------------- K4: attention via gathered projections + residual + BN1 stats ----------------
// 128 threads = 2 points; thread owns channel c = t%64; head = c>>4 (16-lane shfl segments)
__global__ void k_attn(const float* __restrict__ x) {
    __shared__ int   sidx[2][32];
    __shared__ float sred[128];
    int t  = threadIdx.x;
    int pt = t >> 6;
    int c  = t & 63;
    int P  = blockIdx.x*2 + pt;        // global row = b*4096 + n
    int b  = P >> 12;
    int n  = P & 4095;
    if (c < 32) sidx[pt][c] = g_idx[(size_t)P*KK + c];
    __syncthreads();
    size_t rb = (size_t)P*CC;
    float qc  = g_Pq[rb + c];
    float pkn = g_Pk[rb + c];
    float pvn = g_Pv[rb + c];
    size_t bbase = (size_t)b << 12;
    float e[32];
#pragma unroll
    for (int j = 0; j < 32; j++) {
        int m = sidx[pt][j];
        float p = qc * (g_Pk[(bbase + m)*CC + c] - pkn);
        p += __shfl_xor_sync(0xffffffffu, p, 8);
        p += __shfl_xor_sync(0xffffffffu, p, 4);
        p += __shfl_xor_sync(0xffffffffu, p, 2);
        p += __shfl_xor_sync(0xffffffffu, p, 1);
        e[j] = p * 0.25f;                     // / sqrt(D), D=16
    }
    float mx = e[0];
#pragma unroll
    for (int j=1;j<32;j++) mx = fmaxf(mx, e[j]);
    float ssum = 0.f;
#pragma unroll
    for (int j=0;j<32;j++){ e[j] = __expf(e[j]-mx); ssum += e[j]; }
    float inv = 1.f/ssum;
    float acc = 0.f;
#pragma unroll
    for (int j=0;j<32;j++){
        int m = sidx[pt][j];
        acc += e[j] * g_Pv[(bbase + m)*CC + c];
    }
    // sum_j w_j*(Pv_j - pvn) = inv*sum(e_j*Pv_j) - pvn  (weights sum to 1)
    float outv = acc*inv - pvn;
    float y = x[(size_t)b*CC*NN + (size_t)c*NN + n] + outv;
    g_y1[rb + c] = y;
    // BN1 partial stats
    sred[t] = y; __syncthreads();
    if (t < 64) atomicAdd(&g_stats[c], sred[t] + sred[t+64]);
    __syncthreads();
    sred[t] = y*y; __syncthreads();
    if (t < 64) atomicAdd(&g_stats[64+c], sred[t] + sred[t+64]);
}

// ---------------- K6: BN1 apply + MLP (fused, weights resident) + BN2 stats ----------------
// grid 1024 (32 points/block), 256 threads, dyn smem 172672B
__global__ void __launch_bounds__(256, 1)
k_mlp(const float* __restrict__ w1, const float* __restrict__ w2,
      const float* __restrict__ g1, const float* __restrict__ b1) {
    extern __shared__ float sm[];
    float* sW1  = sm;                      // [c*257+o]  (64 x 256, padded)
    float* sW2  = sm + 16448;              // [c*257+o]  (64 rows over 256 o)
    float* sf1  = sm + 2*16448;            // [p*65+c]   (32 x 64)
    float* shid = sm + 2*16448 + 2080;     // [p*256+o]  (32 x 256)
    __shared__ float sred[256];
    int t = threadIdx.x;
    int rowbase = blockIdx.x * 32;
#pragma unroll
    for (int s = 0; s < 64; s++) {
        int i = t + 256*s; int o = i >> 6, c = i & 63;
        sW1[c*257 + o] = w1[i];
    }
#pragma unroll
    for (int s = 0; s < 64; s++) {
        int i = t + 256*s; int c = i >> 8, o = i & 255;
        sW2[c*257 + o] = w2[i];
    }
    const float invN = 1.f/32768.f;
#pragma unroll
    for (int s = 0; s < 8; s++) {
        int i = t + 256*s; int p = i >> 6, c = i & 63;
        float mu  = g_stats[c]*invN;
        float var = g_stats[64+c]*invN - mu*mu;
        float v = g_y1[(size_t)(rowbase+p)*CC + c];
        sf1[p*65 + c] = (v - mu)*rsqrtf(var + EPSB)*g1[c] + b1[c];
    }
    __syncthreads();
    // hid = LeakyReLU(f1 @ W1^T): thread owns output channel o = t
    {
        int o = t;
#pragma unroll
        for (int pb = 0; pb < 4; pb++) {
            float acc[8];
#pragma unroll
            for (int p=0;p<8;p++) acc[p]=0.f;
#pragma unroll
            for (int cc2 = 0; cc2 < 64; cc2++) {
                float w = sW1[cc2*257 + o];
#pragma unroll
                for (int p=0;p<8;p++) acc[p] += sf1[(pb*8+p)*65 + cc2]*w;
            }
#pragma unroll
            for (int p=0;p<8;p++){
                float h = acc[p];
                shid[(pb*8+p)*256 + o] = h > 0.f ? h : 0.2f*h;
            }
        }
    }
    __syncthreads();
    // ff = hid @ W2^T; y2 = f1 + ff; BN2 partial stats
    {
        int c = t & 63; int pg = t >> 6;
        float acc[8];
#pragma unroll
        for (int q=0;q<8;q++) acc[q]=0.f;
#pragma unroll 16
        for (int oo = 0; oo < 256; oo++) {
            float w = sW2[c*257 + oo];
#pragma unroll
            for (int q=0;q<8;q++) acc[q] += shid[(pg*8+q)*256 + oo]*w;
        }
        float psum=0.f, psq=0.f;
#pragma unroll
        for (int q=0;q<8;q++){
            int p = pg*8+q;
            float y = sf1[p*65 + c] + acc[q];
            g_y2[(size_t)(rowbase+p)*CC + c] = y;
            psum += y; psq += y*y;
        }
        sred[t]=psum; __syncthreads();
        if (t<64){
            float s2=sred[t]+sred[t+64]+sred[t+128]+sred[t+192];
            atomicAdd(&g_stats[128+t], s2);
        }
        __syncthreads();
        sred[t]=psq; __syncthreads();
        if (t<64){
            float s2=sred[t]+sred[t+64]+sred[t+128]+sred[t+192];
            atomicAdd(&g_stats[192+t], s2);
        }
    }
}

// ---------------- K7: BN2 apply + transpose to (B,C,N) ----------------
__global__ void k_final(float* __restrict__ out, const float* __restrict__ g2,
                        const float* __restrict__ b2) {
    __shared__ float tile[64*65];
    int t = threadIdx.x;
    int b  = blockIdx.x >> 6;
    int n0 = (blockIdx.x & 63)*64;
    const float invN = 1.f/32768.f;
#pragma unroll
    for (int s = 0; s < 16; s++) {
        int i = t + 256*s; int p = i >> 6, c = i & 63;
        float mu  = g_stats[128+c]*invN;
        float var = g_stats[192+c]*invN - mu*mu;
        float v = g_y2[(size_t)(b*NN + n0 + p)*CC + c];
        tile[c*65 + p] = (v-mu)*rsqrtf(var+EPSB)*g2[c] + b2[c];
    }
    __syncthreads();
#pragma unroll
    for (int s = 0; s < 16; s++) {
        int i = t + 256*s; int c = i >> 6, p = i & 63;
        out[(size_t)b*CC*NN + (size_t)c*NN + n0 + p] = tile[c*65 + p];
    }
}

// ---------------- launch ----------------
extern "C" void kernel_launch(void* const* d_in, const int* in_sizes, int n_in,
                              void* d_out, int out_size) {
    const float* x  = (const float*)d_in[0];
    const float* wq = (const float*)d_in[1];
    const float* wk = (const float*)d_in[2];
    const float* wv = (const float*)d_in[3];
    const float* w1 = (const float*)d_in[4];
    const float* w2 = (const float*)d_in[5];
    const float* g1 = (const float*)d_in[6];
    const float* b1 = (const float*)d_in[7];
    const float* g2 = (const float*)d_in[8];
    const float* b2 = (const float*)d_in[9];
    float* out = (float*)d_out;

    const int PROJ_SMEM = 4*4160*4;        // 66560
    const int DIST_SMEM = 2*64*132*4;      // 67584
    const int MLP_SMEM  = (2*16448 + 2080 + 32*256)*4;   // 172672
    cudaFuncSetAttribute(k_proj, cudaFuncAttributeMaxDynamicSharedMemorySize, PROJ_SMEM);
    cudaFuncSetAttribute(k_dist, cudaFuncAttributeMaxDynamicSharedMemorySize, DIST_SMEM);
    cudaFuncSetAttribute(k_mlp,  cudaFuncAttributeMaxDynamicSharedMemorySize, MLP_SMEM);

    k_zero<<<1, 256>>>();
    k_proj<<<512, 256, PROJ_SMEM>>>(x, wq, wk, wv);
    k_dist<<<dim3(32,32,8), 256, DIST_SMEM>>>(x);
    k_topk<<<NPTS, 256>>>();
    k_attn<<<NPTS/2, 128>>>(x);
    k_mlp<<<NPTS/32, 256, MLP_SMEM>>>(w1, w2, g1, b1);
    k_final<<<512, 256>>>(out, g2, b2);
}

// round 2
// speedup vs baseline: 1.2698x; 1.2698x over previous
#include <cuda_runtime.h>
#include <math.h>

#define BB 8
#define CC 64
#define NN 4096
#define KK 32
#define NPTS (BB*NN)          // 32768
#define EPSB 1e-5f
#define NEG_INF (-3.4e38f)

// ---------------- device scratch (static, allocation-free) ----------------
__device__ float g_Pq[NPTS*CC];
__device__ float g_Pk[NPTS*CC];
__device__ float g_Pv[NPTS*CC];
__device__ float g_sq[NPTS];
__device__ float g_score[(size_t)NPTS*NN];   // 512 MB: ranking scores 2*G - sq[m]
__device__ int   g_idx[NPTS*KK];
__device__ float g_y1[(size_t)NPTS*CC];
__device__ float g_y2[(size_t)NPTS*CC];
__device__ float g_stats[256];               // [sum1|sumsq1|sum2|sumsq2] x 64ch

// ---------------- zero stats (graph-replay safe) ----------------
__global__ void k_zero() { g_stats[threadIdx.x] = 0.f; }

// ---------------- K1: feat projections Pq/Pk/Pv + sq ----------------
__global__ void k_proj(const float* __restrict__ x, const float* __restrict__ wq,
                       const float* __restrict__ wk, const float* __restrict__ wv) {
    extern __shared__ float sm[];
    float* sW = sm;              // 3 * 64*65, layout [w][c*65+o] (transposed, padded)
    float* sf = sm + 3*4160;     // 64*65, layout [p*65+c]
    int t = threadIdx.x;
    int b  = blockIdx.x >> 6;
    int n0 = (blockIdx.x & 63) * 64;
    const float* ws[3] = {wq, wk, wv};
#pragma unroll
    for (int w = 0; w < 3; w++)
#pragma unroll
        for (int s = 0; s < 16; s++) {
            int i = t + 256*s; int o = i >> 6, c = i & 63;
            sW[w*4160 + c*65 + o] = ws[w][i];
        }
    const float* xb = x + (size_t)b*CC*NN;
#pragma unroll
    for (int s = 0; s < 16; s++) {
        int i = t + 256*s; int c = i >> 6, p = i & 63;
        sf[p*65 + c] = xb[c*NN + n0 + p];
    }
    __syncthreads();
    if (t < 64) {
        float s = 0.f;
#pragma unroll
        for (int c = 0; c < 64; c++) { float v = sf[t*65+c]; s += v*v; }
        g_sq[b*NN + n0 + t] = s;
    }
    float* outs[3] = {g_Pq, g_Pk, g_Pv};
#pragma unroll
    for (int w = 0; w < 3; w++)
#pragma unroll
        for (int s = 0; s < 16; s++) {
            int i = t + 256*s; int p = i >> 6, o = i & 63;
            float acc = 0.f;
#pragma unroll
            for (int c = 0; c < 64; c++)
                acc += sf[p*65+c] * sW[w*4160 + c*65 + o];
            outs[w][(size_t)(b*NN + n0 + p)*CC + o] = acc;
        }
}

// ---------------- K2: symmetric distance-score GEMM ----------------
__global__ void __launch_bounds__(256, 2)
k_dist(const float* __restrict__ x) {
    int bx = blockIdx.x, by = blockIdx.y, b = blockIdx.z;
    if (by > bx) return;
    extern __shared__ float sm[];
    float* As = sm;              // [k][i] 64 x 132
    float* Bs = sm + 64*132;
    int n0 = by*128, m0 = bx*128;
    const float* xb = x + (size_t)b*CC*NN;   // x is [c][n] = featT already
    int t = threadIdx.x;
#pragma unroll
    for (int s = 0; s < 32; s++) {
        int j = t + 256*s; int k = j >> 7, i = j & 127;
        As[k*132+i] = xb[k*NN + n0 + i];
        Bs[k*132+i] = xb[k*NN + m0 + i];
    }
    __syncthreads();
    int tx = t & 15, ty = t >> 4;
    float acc[8][8];
#pragma unroll
    for (int i=0;i<8;i++)
#pragma unroll
        for (int j=0;j<8;j++) acc[i][j]=0.f;
#pragma unroll 8
    for (int k = 0; k < 64; k++) {
        float av[8], bv[8];
        float4 a0 = *(const float4*)(As + k*132 + ty*8);
        float4 a1 = *(const float4*)(As + k*132 + ty*8 + 4);
        float4 b0 = *(const float4*)(Bs + k*132 + tx*8);
        float4 b1 = *(const float4*)(Bs + k*132 + tx*8 + 4);
        av[0]=a0.x; av[1]=a0.y; av[2]=a0.z; av[3]=a0.w;
        av[4]=a1.x; av[5]=a1.y; av[6]=a1.z; av[7]=a1.w;
        bv[0]=b0.x; bv[1]=b0.y; bv[2]=b0.z; bv[3]=b0.w;
        bv[4]=b1.x; bv[5]=b1.y; bv[6]=b1.z; bv[7]=b1.w;
#pragma unroll
        for (int i=0;i<8;i++)
#pragma unroll
            for (int j=0;j<8;j++) acc[i][j] += av[i]*bv[j];
    }
    const float* sqb = g_sq + b*NN;
    float sqm[8], sqn[8];
#pragma unroll
    for (int j=0;j<8;j++) sqm[j] = sqb[m0 + tx*8 + j];
#pragma unroll
    for (int i=0;i<8;i++) sqn[i] = sqb[n0 + ty*8 + i];
    float* base = g_score + (size_t)b*NN*NN;
#pragma unroll
    for (int i=0;i<8;i++) {
        int row = n0 + ty*8 + i;
        float* d = base + (size_t)row*NN + m0 + tx*8;
        float4 v0, v1;
        v0.x = 2.f*acc[i][0]-sqm[0]; v0.y = 2.f*acc[i][1]-sqm[1];
        v0.z = 2.f*acc[i][2]-sqm[2]; v0.w = 2.f*acc[i][3]-sqm[3];
        v1.x = 2.f*acc[i][4]-sqm[4]; v1.y = 2.f*acc[i][5]-sqm[5];
        v1.z = 2.f*acc[i][6]-sqm[6]; v1.w = 2.f*acc[i][7]-sqm[7];
        *(float4*)(d)   = v0;
        *(float4*)(d+4) = v1;
    }
    if (bx != by) {
#pragma unroll
        for (int j=0;j<8;j++) {
            int rowT = m0 + tx*8 + j;
            float* d = base + (size_t)rowT*NN + n0 + ty*8;
            float4 v0, v1;
            v0.x = 2.f*acc[0][j]-sqn[0]; v0.y = 2.f*acc[1][j]-sqn[1];
            v0.z = 2.f*acc[2][j]-sqn[2]; v0.w = 2.f*acc[3][j]-sqn[3];
            v1.x = 2.f*acc[4][j]-sqn[4]; v1.y = 2.f*acc[5][j]-sqn[5];
            v1.z = 2.f*acc[6][j]-sqn[6]; v1.w = 2.f*acc[7][j]-sqn[7];
            *(float4*)(d)   = v0;
            *(float4*)(d+4) = v1;
        }
    }
}

// ---------------- K3: top-32 via single-pass radix select ----------------
// One block per row, 256 threads. 2048-bin histogram on top-11 bits of the
// order-preserving key, descending scan to find threshold bin, direct-emit
// strictly-above indices, small argmax rounds only inside the threshold bin.
__device__ __forceinline__ unsigned fkey(float f) {
    unsigned u = __float_as_uint(f);
    return u ^ ((u & 0x80000000u) ? 0xFFFFFFFFu : 0x80000000u);
}

__global__ void __launch_bounds__(256) k_topk() {
    __shared__ unsigned shist[2048];
    __shared__ float cval[4096];
    __shared__ int   cidx[4096];
    __shared__ unsigned wsum[8];
    __shared__ int s_bstar, s_cnthi;
    __shared__ int s_ncnt, s_ccnt;
    __shared__ float rwv[8];
    __shared__ int   rwi[8], rwp[8];
    __shared__ int s_win;

    int t = threadIdx.x;
    size_t row = blockIdx.x;
    const float* src = g_score + row*(size_t)NN;

#pragma unroll
    for (int i = 0; i < 8; i++) shist[t + 256*i] = 0u;
    if (t == 0) { s_ncnt = 0; s_ccnt = 0; }
    __syncthreads();

    // load 16 values/thread into registers, histogram
    float v[16];
    unsigned kb[16];
#pragma unroll
    for (int i = 0; i < 16; i++) {
        v[i] = src[i*256 + t];
        kb[i] = fkey(v[i]) >> 21;
        atomicAdd(&shist[kb[i]], 1u);
    }
    __syncthreads();

    // descending-bin scan: thread t owns bins 2047-8t .. 2047-8t-7
    unsigned part = 0;
    unsigned hloc[8];
#pragma unroll
    for (int i = 0; i < 8; i++) { hloc[i] = shist[2047 - (t*8 + i)]; part += hloc[i]; }
    unsigned lane = t & 31, w = t >> 5;
    unsigned val = part;
#pragma unroll
    for (int off = 1; off < 32; off <<= 1) {
        unsigned nv = __shfl_up_sync(0xffffffffu, val, off);
        if (lane >= off) val += nv;
    }
    if (lane == 31) wsum[w] = val;
    __syncthreads();
    unsigned woff = 0;
#pragma unroll
    for (int i = 0; i < 8; i++) woff += (i < (int)w) ? wsum[i] : 0u;
    unsigned incl = val + woff;
    unsigned excl = incl - part;
    if (excl < KK && incl >= KK) {
        unsigned acc = excl;
#pragma unroll
        for (int i = 0; i < 8; i++) {
            if (acc + hloc[i] >= KK) { s_bstar = 2047 - (t*8 + i); s_cnthi = (int)acc; break; }
            acc += hloc[i];
        }
    }
    __syncthreads();
    int bstar = s_bstar;
    int cnthi = s_cnthi;

    // collect: strictly-above bins -> direct emit; threshold bin -> candidates
    int* rowidx = g_idx + row*KK;
#pragma unroll
    for (int i = 0; i < 16; i++) {
        int bin = (int)kb[i];
        if (bin > bstar) {
            int pos = atomicAdd(&s_ncnt, 1);
            rowidx[pos] = i*256 + t;
        } else if (bin == bstar) {
            int pos = atomicAdd(&s_ccnt, 1);
            cval[pos] = v[i];
            cidx[pos] = i*256 + t;
        }
    }
    __syncthreads();

    int C = s_ccnt;
    int need = KK - cnthi;
    for (int r = 0; r < need; r++) {
        float lv = NEG_INF; int li = 0x7fffffff, lp = -1;
        for (int i = t; i < C; i += 256) {
            float vv = cval[i];
            int ii = cidx[i];
            if (vv > lv || (vv == lv && ii < li)) { lv = vv; li = ii; lp = i; }
        }
#pragma unroll
        for (int off = 16; off > 0; off >>= 1) {
            float ov = __shfl_down_sync(0xffffffffu, lv, off);
            int   oi = __shfl_down_sync(0xffffffffu, li, off);
            int   op = __shfl_down_sync(0xffffffffu, lp, off);
            if (ov > lv || (ov == lv && oi < li)) { lv = ov; li = oi; lp = op; }
        }
        if (lane == 0) { rwv[w] = lv; rwi[w] = li; rwp[w] = lp; }
        __syncthreads();
        if (t == 0) {
            float bv = rwv[0]; int bi = rwi[0], bp = rwp[0];
#pragma unroll
            for (int j = 1; j < 8; j++) {
                if (rwv[j] > bv || (rwv[j] == bv && rwi[j] < bi)) { bv = rwv[j]; bi = rwi[j]; bp = rwp[j]; }
            }
            rowidx[cnthi + r] = bi;
            s_win = bp;
        }
        __syncthreads();
        if (t == 0) cval[s_win] = NEG_INF;
        __syncthreads();
    }
}

// ---------------- K4: attention via gathered projections + residual + BN1 stats ----------------
__global__ void k_attn(const float* __restrict__ x) {
    __shared__ int   sidx[2][32];
    __shared__ float sred[128];
    int t  = threadIdx.x;
    int pt = t >> 6;
    int c  = t & 63;
    int P  = blockIdx.x*2 + pt;        // global row = b*4096 + n
    int b  = P >> 12;
    int n  = P & 4095;
    if (c < 32) sidx[pt][c] = g_idx[(size_t)P*KK + c];
    __syncthreads();
    size_t rb = (size_t)P*CC;
    float qc  = g_Pq[rb + c];
    float pkn = g_Pk[rb + c];
    float pvn = g_Pv[rb + c];
    size_t bbase = (size_t)b << 12;
    float e[32];
#pragma unroll
    for (int j = 0; j < 32; j++) {
        int m = sidx[pt][j];
        float p = qc * (g_Pk[(bbase + m)*CC + c] - pkn);
        p += __shfl_xor_sync(0xffffffffu, p, 8);
        p += __shfl_xor_sync(0xffffffffu, p, 4);
        p += __shfl_xor_sync(0xffffffffu, p, 2);
        p += __shfl_xor_sync(0xffffffffu, p, 1);
        e[j] = p * 0.25f;                     // / sqrt(D), D=16
    }
    float mx = e[0];
#pragma unroll
    for (int j=1;j<32;j++) mx = fmaxf(mx, e[j]);
    float ssum = 0.f;
#pragma unroll
    for (int j=0;j<32;j++){ e[j] = __expf(e[j]-mx); ssum += e[j]; }
    float inv = 1.f/ssum;
    float acc = 0.f;
#pragma unroll
    for (int j=0;j<32;j++){
        int m = sidx[pt][j];
        acc += e[j] * g_Pv[(bbase + m)*CC + c];
    }
    float outv = acc*inv - pvn;
    float y = x[(size_t)b*CC*NN + (size_t)c*NN + n] + outv;
    g_y1[rb + c] = y;
    sred[t] = y; __syncthreads();
    if (t < 64) atomicAdd(&g_stats[c], sred[t] + sred[t+64]);
    __syncthreads();
    sred[t] = y*y; __syncthreads();
    if (t < 64) atomicAdd(&g_stats[64+c], sred[t] + sred[t+64]);
}

// ---------------- K6: BN1 apply + MLP (fused, weights resident) + BN2 stats ----------------
__global__ void __launch_bounds__(256, 1)
k_mlp(const float* __restrict__ w1, const float* __restrict__ w2,
      const float* __restrict__ g1, const float* __restrict__ b1) {
    extern __shared__ float sm[];
    float* sW1  = sm;                      // [c*257+o]
    float* sW2  = sm + 16448;              // [c*257+o]
    float* sf1  = sm + 2*16448;            // [p*65+c]
    float* shid = sm + 2*16448 + 2080;     // [p*256+o]
    __shared__ float sred[256];
    int t = threadIdx.x;
    int rowbase = blockIdx.x * 32;
#pragma unroll
    for (int s = 0; s < 64; s++) {
        int i = t + 256*s; int o = i >> 6, c = i & 63;
        sW1[c*257 + o] = w1[i];
    }
#pragma unroll
    for (int s = 0; s < 64; s++) {
        int i = t + 256*s; int c = i >> 8, o = i & 255;
        sW2[c*257 + o] = w2[i];
    }
    const float invN = 1.f/32768.f;
#pragma unroll
    for (int s = 0; s < 8; s++) {
        int i = t + 256*s; int p = i >> 6, c = i & 63;
        float mu  = g_stats[c]*invN;
        float var = g_stats[64+c]*invN - mu*mu;
        float v = g_y1[(size_t)(rowbase+p)*CC + c];
        sf1[p*65 + c] = (v - mu)*rsqrtf(var + EPSB)*g1[c] + b1[c];
    }
    __syncthreads();
    {
        int o = t;
#pragma unroll
        for (int pb = 0; pb < 4; pb++) {
            float acc[8];
#pragma unroll
            for (int p=0;p<8;p++) acc[p]=0.f;
#pragma unroll
            for (int cc2 = 0; cc2 < 64; cc2++) {
                float w = sW1[cc2*257 + o];
#pragma unroll
                for (int p=0;p<8;p++) acc[p] += sf1[(pb*8+p)*65 + cc2]*w;
            }
#pragma unroll
            for (int p=0;p<8;p++){
                float h = acc[p];
                shid[(pb*8+p)*256 + o] = h > 0.f ? h : 0.2f*h;
            }
        }
    }
    __syncthreads();
    {
        int c = t & 63; int pg = t >> 6;
        float acc[8];
#pragma unroll
        for (int q=0;q<8;q++) acc[q]=0.f;
#pragma unroll 16
        for (int oo = 0; oo < 256; oo++) {
            float w = sW2[c*257 + oo];
#pragma unroll
            for (int q=0;q<8;q++) acc[q] += shid[(pg*8+q)*256 + oo]*w;
        }
        float psum=0.f, psq=0.f;
#pragma unroll
        for (int q=0;q<8;q++){
            int p = pg*8+q;
            float y = sf1[p*65 + c] + acc[q];
            g_y2[(size_t)(rowbase+p)*CC + c] = y;
            psum += y; psq += y*y;
        }
        sred[t]=psum; __syncthreads();
        if (t<64){
            float s2=sred[t]+sred[t+64]+sred[t+128]+sred[t+192];
            atomicAdd(&g_stats[128+t], s2);
        }
        __syncthreads();
        sred[t]=psq; __syncthreads();
        if (t<64){
            float s2=sred[t]+sred[t+64]+sred[t+128]+sred[t+192];
            atomicAdd(&g_stats[192+t], s2);
        }
    }
}

// ---------------- K7: BN2 apply + transpose to (B,C,N) ----------------
__global__ void k_final(float* __restrict__ out, const float* __restrict__ g2,
                        const float* __restrict__ b2) {
    __shared__ float tile[64*65];
    int t = threadIdx.x;
    int b  = blockIdx.x >> 6;
    int n0 = (blockIdx.x & 63)*64;
    const float invN = 1.f/32768.f;
#pragma unroll
    for (int s = 0; s < 16; s++) {
        int i = t + 256*s; int p = i >> 6, c = i & 63;
        float mu  = g_stats[128+c]*invN;
        float var = g_stats[192+c]*invN - mu*mu;
        float v = g_y2[(size_t)(b*NN + n0 + p)*CC + c];
        tile[c*65 + p] = (v-mu)*rsqrtf(var+EPSB)*g2[c] + b2[c];
    }
    __syncthreads();
#pragma unroll
    for (int s = 0; s < 16; s++) {
        int i = t + 256*s; int c = i >> 6, p = i & 63;
        out[(size_t)b*CC*NN + (size_t)c*NN + n0 + p] = tile[c*65 + p];
    }
}

// ---------------- launch ----------------
extern "C" void kernel_launch(void* const* d_in, const int* in_sizes, int n_in,
                              void* d_out, int out_size) {
    const float* x  = (const float*)d_in[0];
    const float* wq = (const float*)d_in[1];
    const float* wk = (const float*)d_in[2];
    const float* wv = (const float*)d_in[3];
    const float* w1 = (const float*)d_in[4];
    const float* w2 = (const float*)d_in[5];
    const float* g1 = (const float*)d_in[6];
    const float* b1 = (const float*)d_in[7];
    const float* g2 = (const float*)d_in[8];
    const float* b2 = (const float*)d_in[9];
    float* out = (float*)d_out;

    const int PROJ_SMEM = 4*4160*4;        // 66560
    const int DIST_SMEM = 2*64*132*4;      // 67584
    const int MLP_SMEM  = (2*16448 + 2080 + 32*256)*4;   // 172672
    cudaFuncSetAttribute(k_proj, cudaFuncAttributeMaxDynamicSharedMemorySize, PROJ_SMEM);
    cudaFuncSetAttribute(k_dist, cudaFuncAttributeMaxDynamicSharedMemorySize, DIST_SMEM);
    cudaFuncSetAttribute(k_mlp,  cudaFuncAttributeMaxDynamicSharedMemorySize, MLP_SMEM);

    k_zero<<<1, 256>>>();
    k_proj<<<512, 256, PROJ_SMEM>>>(x, wq, wk, wv);
    k_dist<<<dim3(32,32,8), 256, DIST_SMEM>>>(x);
    k_topk<<<NPTS, 256>>>();
    k_attn<<<NPTS/2, 128>>>(x);
    k_mlp<<<NPTS/32, 256, MLP_SMEM>>>(w1, w2, g1, b1);
    k_final<<<512, 256>>>(out, g2, b2);
}